// round 13
// baseline (speedup 1.0000x reference)
#include <cuda_runtime.h>
#include <cstdint>

// 2x2 Haar DWT, fp32.
// Input:  x  (16, 1, 2048, 2048)  -> 64M floats
// Output: [ll | lh | hl | hh], each (16, 1, 1024, 1024), concatenated -> 64M floats
//
// ll = 0.5*( a + b + c + d)
// lh = 0.5*(-a + b - c + d)
// hl = 0.5*(-a - b + c + d)
// hh = 0.5*( a - b - c + d)
// _safe(): non-finite -> 0 on inputs and outputs.
//
// R13: vertical 2-row stacking. Each thread: same 4 output cols as the proven
// R3 layout (32B warp stride per LDG — L1-friendly), but TWO adjacent output
// rows. 8 front-batched LDG.128 then 8 STG.128 per thread: doubles the
// same-direction DRAM burst length per warp (fewer R/W turnarounds) and
// doubles per-thread MLP, at identical per-instruction coalescing.

static constexpr int B   = 16;
static constexpr int H   = 2048;
static constexpr int W   = 2048;
static constexpr int OH  = H / 2;   // 1024
static constexpr int OW  = W / 2;   // 1024
static constexpr long long SUB_ELEMS = (long long)B * OH * OW;  // 16M per subband

__device__ __forceinline__ float safef(float v) {
    // finite check via exponent bits (robust under fast-math)
    return ((__float_as_uint(v) & 0x7f800000u) == 0x7f800000u) ? 0.0f : v;
}

__device__ __forceinline__ float4 safe4(float4 v) {
    v.x = safef(v.x); v.y = safef(v.y); v.z = safef(v.z); v.w = safef(v.w);
    return v;
}

// Haar butterfly for one 4-col group: p = (a b a b ...) row, q = (c d c d ...) row
__device__ __forceinline__ void haar4(const float4 p0, const float4 p1,
                                      const float4 q0, const float4 q1,
                                      float4& ll, float4& lh, float4& hl, float4& hh) {
    const float a[4] = {p0.x, p0.z, p1.x, p1.z};
    const float b[4] = {p0.y, p0.w, p1.y, p1.w};
    const float c[4] = {q0.x, q0.z, q1.x, q1.z};
    const float d[4] = {q0.y, q0.w, q1.y, q1.w};
    float* llp = &ll.x; float* lhp = &lh.x; float* hlp = &hl.x; float* hhp = &hh.x;
#pragma unroll
    for (int i = 0; i < 4; i++) {
        float s_ab = a[i] + b[i];
        float d_ab = b[i] - a[i];
        float s_cd = c[i] + d[i];
        float d_cd = d[i] - c[i];
        llp[i] = safef(0.5f * (s_ab + s_cd));
        lhp[i] = safef(0.5f * (d_ab + d_cd));
        hlp[i] = safef(0.5f * (s_cd - s_ab));
        hhp[i] = safef(0.5f * (d_cd - d_ab));
    }
}

__global__ __launch_bounds__(256)
void dwt2d_haar_kernel(const float* __restrict__ x, float* __restrict__ out) {
    // Each thread: 4 output cols x 2 output rows.
    // Total threads = B * (OH/2) * (OW/4) = 16 * 512 * 256 = 2,097,152
    const int t = blockIdx.x * blockDim.x + threadIdx.x;
    const int g  = t & 255;               // col group (4 cols)
    const int rn = t >> 8;                // row-pair index within all batches
    const int rp = rn & (OH / 2 - 1);     // output row pair 0..511
    const int n  = rn >> 9;
    if (n >= B) return;

    const int r0 = 2 * rp;                // first output row of the pair

    // 4 input rows: 4*rp .. 4*rp+3
    const long long in_base = (long long)n * H * W + (long long)(4 * rp) * W + 8 * g;
    const float4* i0 = (const float4*)(x + in_base);           // input row 4rp
    const float4* i1 = (const float4*)(x + in_base + W);       // 4rp+1
    const float4* i2 = (const float4*)(x + in_base + 2 * W);   // 4rp+2
    const float4* i3 = (const float4*)(x + in_base + 3 * W);   // 4rp+3

    // Front-batch all 8 loads (MLP=8), each wavefront 32B-stride (R3 shape)
    float4 p0 = __ldcs(i0 + 0), p1 = __ldcs(i0 + 1);
    float4 q0 = __ldcs(i1 + 0), q1 = __ldcs(i1 + 1);
    float4 s0 = __ldcs(i2 + 0), s1 = __ldcs(i2 + 1);
    float4 u0 = __ldcs(i3 + 0), u1 = __ldcs(i3 + 1);
    p0 = safe4(p0); p1 = safe4(p1); q0 = safe4(q0); q1 = safe4(q1);
    s0 = safe4(s0); s1 = safe4(s1); u0 = safe4(u0); u1 = safe4(u1);

    float4 llA, lhA, hlA, hhA, llB, lhB, hlB, hhB;
    haar4(p0, p1, q0, q1, llA, lhA, hlA, hhA);   // output row r0
    haar4(s0, s1, u0, u1, llB, lhB, hlB, hhB);   // output row r0+1

    const long long out_base = (long long)n * OH * OW + (long long)r0 * OW + 4 * g;
    float* o = out + out_base;
    // 8 stores, grouped per subband (row pair = 4KB apart within subband)
    __stcs((float4*)(o),                          llA);
    __stcs((float4*)(o + OW),                     llB);
    __stcs((float4*)(o + SUB_ELEMS),              lhA);
    __stcs((float4*)(o + SUB_ELEMS + OW),         lhB);
    __stcs((float4*)(o + 2 * SUB_ELEMS),          hlA);
    __stcs((float4*)(o + 2 * SUB_ELEMS + OW),     hlB);
    __stcs((float4*)(o + 3 * SUB_ELEMS),          hhA);
    __stcs((float4*)(o + 3 * SUB_ELEMS + OW),     hhB);
}

extern "C" void kernel_launch(void* const* d_in, const int* in_sizes, int n_in,
                              void* d_out, int out_size) {
    const float* x = (const float*)d_in[0];
    float* out = (float*)d_out;
    const long long total_threads = (long long)B * (OH / 2) * (OW / 4);  // 2,097,152
    const int block = 256;
    const int grid = (int)((total_threads + block - 1) / block);         // 8192
    dwt2d_haar_kernel<<<grid, block>>>(x, out);
}

// round 14
// speedup vs baseline: 1.0027x; 1.0027x over previous
#include <cuda_runtime.h>
#include <cstdint>

// 2x2 Haar DWT, fp32.
// Input:  x  (16, 1, 2048, 2048)  -> 64M floats
// Output: [ll | lh | hl | hh], each (16, 1, 1024, 1024), concatenated -> 64M floats
//
// ll = 0.5*( a + b + c + d)
// lh = 0.5*(-a + b - c + d)
// hl = 0.5*(-a - b + c + d)
// hh = 0.5*( a - b - c + d)
// _safe(): non-finite -> 0 on inputs and outputs.
//
// FINAL (R14): best-measured shape (R12: 4 output cols/thread, 16384 CTAs x
// 256 thr, .cs loads+stores) with pure 32-bit indexing (all offsets < 2^26
// elements). Kernel is at the B300 LTS throughput cap (~6300 B/cyc,
// path-independent): 6.48 TB/s achieved on minimal 512MB traffic. Burst
// shaping (R4/R9/R13) and cache policy (R5/R12) all confirmed non-levers.

static constexpr int B   = 16;
static constexpr int H   = 2048;
static constexpr int W   = 2048;
static constexpr int OH  = H / 2;   // 1024
static constexpr int OW  = W / 2;   // 1024
static constexpr int SUB_ELEMS = B * OH * OW;   // 16,777,216 per subband (fits int)

__device__ __forceinline__ float safef(float v) {
    // finite check via exponent bits (robust under fast-math)
    return ((__float_as_uint(v) & 0x7f800000u) == 0x7f800000u) ? 0.0f : v;
}

__device__ __forceinline__ float4 safe4(float4 v) {
    v.x = safef(v.x); v.y = safef(v.y); v.z = safef(v.z); v.w = safef(v.w);
    return v;
}

__global__ __launch_bounds__(256)
void dwt2d_haar_kernel(const float* __restrict__ x, float* __restrict__ out) {
    // Each thread: 4 output columns of one output row.
    // Total threads = B * OH * (OW/4) = 16 * 1024 * 256 = 4,194,304
    const int t = blockIdx.x * blockDim.x + threadIdx.x;
    // t layout: [n(4b) | r(10b) | g(8b)]
    const int g  = t & 255;               // col group (4 output cols)
    const int rn = t >> 8;                // n*OH + r
    if (rn >= B * OH) return;

    // Input offset: n*H*W + 2r*W + 8g = rn * (2*W) ... since n*H*W + 2r*W = 2*W*(n*OH + r)
    const int in_base  = rn * (2 * W) + 8 * g;          // max 2*2048*16384 = 2^26 ok
    const float4* row0 = (const float4*)(x + in_base);
    const float4* row1 = (const float4*)(x + in_base + W);

    // Front-batched streaming loads (read-once data)
    float4 p0 = __ldcs(row0 + 0);   // a0 b0 a1 b1
    float4 p1 = __ldcs(row0 + 1);   // a2 b2 a3 b3
    float4 q0 = __ldcs(row1 + 0);   // c0 d0 c1 d1
    float4 q1 = __ldcs(row1 + 1);   // c2 d2 c3 d3
    p0 = safe4(p0); p1 = safe4(p1); q0 = safe4(q0); q1 = safe4(q1);

    const float a[4] = {p0.x, p0.z, p1.x, p1.z};
    const float b[4] = {p0.y, p0.w, p1.y, p1.w};
    const float c[4] = {q0.x, q0.z, q1.x, q1.z};
    const float d[4] = {q0.y, q0.w, q1.y, q1.w};

    float4 ll, lh, hl, hh;
    float* llp = &ll.x; float* lhp = &lh.x; float* hlp = &hl.x; float* hhp = &hh.x;
#pragma unroll
    for (int i = 0; i < 4; i++) {
        float s_ab = a[i] + b[i];
        float d_ab = b[i] - a[i];
        float s_cd = c[i] + d[i];
        float d_cd = d[i] - c[i];
        llp[i] = safef(0.5f * (s_ab + s_cd));
        lhp[i] = safef(0.5f * (d_ab + d_cd));
        hlp[i] = safef(0.5f * (s_cd - s_ab));
        hhp[i] = safef(0.5f * (d_cd - d_ab));
    }

    // Output offset: n*OH*OW + r*OW + 4g = rn*OW + 4g
    const int out_base = rn * OW + 4 * g;               // max 2^24, fits int
    float* o = out + out_base;
    __stcs((float4*)(o),                 ll);
    __stcs((float4*)(o + SUB_ELEMS),     lh);
    __stcs((float4*)(o + 2 * SUB_ELEMS), hl);
    __stcs((float4*)(o + 3 * SUB_ELEMS), hh);
}

extern "C" void kernel_launch(void* const* d_in, const int* in_sizes, int n_in,
                              void* d_out, int out_size) {
    const float* x = (const float*)d_in[0];
    float* out = (float*)d_out;
    const int total_threads = B * OH * (OW / 4);          // 4,194,304
    const int block = 256;
    const int grid = total_threads / block;               // 16384
    dwt2d_haar_kernel<<<grid, block>>>(x, out);
}